// round 10
// baseline (speedup 1.0000x reference)
#include <cuda_runtime.h>
#include <math.h>

#define Cc 128
#define Hh 8
#define Dd 16
#define Tt 16
#define NS 100000
#define NF 50000
#define NT 150000
#define EMAX 200000
#define CCx (Cc * Cc)

#define ASTR 132
#define WSTR 136
#define WTILE (128 * WSTR)   // u32 per pre-swizzled weight tile
#define MROWS 64             // CTA M-tile

// ---------------- scratch (device globals; no allocation) ----------------
__device__ float g_x  [(size_t)NT * Cc];
__device__ float g_q  [(size_t)NT * Cc];
__device__ float g_kr0[(size_t)NS * Cc];
__device__ float g_vr0[(size_t)NS * Cc];
__device__ float g_kr1[(size_t)NS * Cc];
__device__ float g_vr1[(size_t)NS * Cc];
__device__ float g_kr2[(size_t)NF * Cc];
__device__ float g_vr2[(size_t)NF * Cc];
__device__ unsigned g_wtf[(size_t)22 * WTILE];
__device__ float g_bc [12 * Cc];
__device__ int g_rowptr[3 * (NS + 1)];
__device__ int g_cursor[NS + 1];
__device__ int g_col[3 * EMAX];
__device__ int g_bsum[256];

// ---------------- helpers ----------------
__device__ __forceinline__ float gelu_tanh(float x) {
    float x3 = x * x * x;
    return 0.5f * x * (1.0f + tanhf(0.7978845608028654f * (x + 0.044715f * x3)));
}
__device__ __forceinline__ unsigned f2tf(float f) {
    unsigned r; asm("cvt.rna.tf32.f32 %0, %1;" : "=r"(r) : "f"(f)); return r;
}

// ---------------- small utility kernels ----------------
__global__ void zero_i(int* p, int n) {
    int i = blockIdx.x * blockDim.x + threadIdx.x;
    if (i < n) p[i] = 0;
}
__global__ void copy_i(const int* a, int* b, int n) {
    int i = blockIdx.x * blockDim.x + threadIdx.x;
    if (i < n) b[i] = a[i];
}

// ---------------- CSR build ----------------
__global__ void hist_kernel(const int* __restrict__ dst, int* __restrict__ rowptr, int E) {
    int e = blockIdx.x * blockDim.x + threadIdx.x;
    if (e < E) atomicAdd(&rowptr[dst[e] + 1], 1);
}
__global__ void scan_blk(int* data, int* bsum, int n) {
    __shared__ int sm[1024];
    int i = blockIdx.x * 1024 + threadIdx.x;
    int v = (i < n) ? data[i] : 0;
    sm[threadIdx.x] = v;
    __syncthreads();
    for (int ofs = 1; ofs < 1024; ofs <<= 1) {
        int t = (threadIdx.x >= ofs) ? sm[threadIdx.x - ofs] : 0;
        __syncthreads();
        sm[threadIdx.x] += t;
        __syncthreads();
    }
    if (i < n) data[i] = sm[threadIdx.x];
    if (threadIdx.x == 1023) bsum[blockIdx.x] = sm[1023];
}
__global__ void scan_top(int* bsum, int nb) {
    if (threadIdx.x == 0) {
        int acc = 0;
        for (int i = 0; i < nb; i++) { int t = bsum[i]; bsum[i] = acc; acc += t; }
    }
}
__global__ void scan_add(int* data, const int* bsum, int n) {
    int i = blockIdx.x * 1024 + threadIdx.x;
    if (i < n) data[i] += bsum[blockIdx.x];
}
__global__ void scatter_kernel(const int* __restrict__ src, const int* __restrict__ dst,
                               int* __restrict__ cursor, int* __restrict__ col, int E) {
    int e = blockIdx.x * blockDim.x + threadIdx.x;
    if (e < E) {
        int pos = atomicAdd(&cursor[dst[e]], 1);
        col[pos] = src[e];
    }
}

// ---------------- prep + compose: 22 pre-swizzled tf32 weight tiles ----------------
__global__ void prep_compose(const float* __restrict__ lin_w, const float* __restrict__ qw,
                             const float* __restrict__ aw,
                             const float* __restrict__ kw, const float* __restrict__ vw,
                             const float* __restrict__ kb, const float* __restrict__ vb,
                             const float* __restrict__ a_rel, const float* __restrict__ m_rel,
                             unsigned* __restrict__ wtf, float* __restrict__ bc) {
    int m = blockIdx.y;
    int k = blockIdx.x;
    int t = threadIdx.x;
    if (m < 10) {
        const float* src = (m < 2) ? lin_w + (size_t)m * CCx
                         : (m < 6) ? qw + (size_t)(m - 2) * CCx
                                   : aw + (size_t)(m - 6) * CCx;
        wtf[(size_t)m * WTILE + k * WSTR + t] = f2tf(src[k * 128 + t]);
        return;
    }
    int comp = m - 10;
    int l = comp / 6, c6 = comp % 6, r = c6 >> 1, isV = c6 & 1;
    int st = (r == 2) ? 1 : 0;
    const float* W = (isV ? vw : kw) + (size_t)(l * 2 + st) * CCx;
    const float* B = (isV ? vb : kb) + (size_t)(l * 2 + st) * Cc;
    const float* A = (isV ? m_rel : a_rel) + (size_t)(l * 3 + r) * Hh * Dd * Dd;
    __shared__ float sw[128];
    __shared__ float sa[2048];
    sw[t] = W[k * 128 + t];
#pragma unroll
    for (int u = 0; u < 16; u++) sa[t + 128 * u] = A[t + 128 * u];
    __syncthreads();
    int h = t >> 4, e = t & 15;
    float s = 0.f;
#pragma unroll
    for (int d = 0; d < 16; d++) s = fmaf(sw[h * 16 + d], sa[h * 256 + d * 16 + e], s);
    wtf[(size_t)m * WTILE + k * WSTR + t] = f2tf(s);
    if (k == 0) {
        float sb = 0.f;
#pragma unroll
        for (int d = 0; d < 16; d++) sb = fmaf(B[h * 16 + d], sa[h * 256 + d * 16 + e], sb);
        bc[comp * Cc + t] = sb;
    }
}

// ---------------- GEMM blocks: 64x128 CTA tile, 256 threads, 2 CTAs/SM ----------------
__device__ __forceinline__ void load_W256(const unsigned* __restrict__ Wt, unsigned* Ws, int t) {
    const float4* src = (const float4*)Wt;
    float4* dst = (float4*)Ws;
#pragma unroll
    for (int u = 0; u < 17; u++) dst[t + 256 * u] = src[t + 256 * u];
}

template <int PRE>
__device__ __forceinline__ void load_A256(const float* __restrict__ A, unsigned* As,
                                          int t, int rowBase, int M) {
#pragma unroll
    for (int u = 0; u < 8; u++) {
        int f = t + 256 * u;          // 0..2047
        int r = f >> 5, c4 = f & 31;
        int gr = rowBase + r;
        float4 v = make_float4(0.f, 0.f, 0.f, 0.f);
        if (gr < M) v = ((const float4*)A)[(size_t)gr * 32 + c4];
        if (PRE == 1) {
            v.x = gelu_tanh(v.x); v.y = gelu_tanh(v.y);
            v.z = gelu_tanh(v.z); v.w = gelu_tanh(v.w);
        }
        unsigned* p = As + r * ASTR + c4 * 4;
        p[0] = f2tf(v.x); p[1] = f2tf(v.y); p[2] = f2tf(v.z); p[3] = f2tf(v.w);
    }
}

__device__ __forceinline__ void mma_tile256(const unsigned* As, const unsigned* Ws,
                                            float acc[2][4][4], int warpM, int warpN,
                                            int gid, int tg) {
#pragma unroll
    for (int mi = 0; mi < 2; mi++)
#pragma unroll
        for (int ni = 0; ni < 4; ni++)
#pragma unroll
            for (int j = 0; j < 4; j++) acc[mi][ni][j] = 0.0f;
#pragma unroll
    for (int kc = 0; kc < 16; kc++) {
        int k0 = kc * 8;
        unsigned a[2][4];
#pragma unroll
        for (int mi = 0; mi < 2; mi++) {
            const unsigned* Ap = As + (warpM * 32 + mi * 16 + gid) * ASTR + k0 + tg;
            a[mi][0] = Ap[0];
            a[mi][1] = Ap[8 * ASTR];
            a[mi][2] = Ap[4];
            a[mi][3] = Ap[8 * ASTR + 4];
        }
        unsigned b[4][2];
#pragma unroll
        for (int ni = 0; ni < 4; ni++) {
            int n = warpN * 32 + ni * 8 + gid;
            b[ni][0] = Ws[(k0 + tg) * WSTR + n];
            b[ni][1] = Ws[(k0 + tg + 4) * WSTR + n];
        }
#pragma unroll
        for (int mi = 0; mi < 2; mi++)
#pragma unroll
            for (int ni = 0; ni < 4; ni++)
                asm volatile(
                    "mma.sync.aligned.m16n8k8.row.col.f32.tf32.tf32.f32 "
                    "{%0,%1,%2,%3},{%4,%5,%6,%7},{%8,%9},{%0,%1,%2,%3};"
                    : "+f"(acc[mi][ni][0]), "+f"(acc[mi][ni][1]),
                      "+f"(acc[mi][ni][2]), "+f"(acc[mi][ni][3])
                    : "r"(a[mi][0]), "r"(a[mi][1]), "r"(a[mi][2]), "r"(a[mi][3]),
                      "r"(b[ni][0]), "r"(b[ni][1]));
    }
}

// ---------------- fused encoder + lin GEMM (relu epilogue) ----------------
__global__ void __launch_bounds__(256, 2)
enc_gemm(const int* __restrict__ tok, const float* __restrict__ emb,
         const unsigned* __restrict__ Wt, const float* __restrict__ bias,
         float* __restrict__ Cout, int M) {
    extern __shared__ unsigned smu[];
    unsigned* Ws = smu;
    unsigned* As = smu + 128 * WSTR;
    int t = threadIdx.x;
    int lane = t & 31, wid = t >> 5;
    int rowBase = blockIdx.x * MROWS;

    load_W256(Wt, Ws, t);   // independent; overlaps with pooling below

    // warp wid pools nodes rowBase + wid*8 .. +7
#pragma unroll
    for (int i = 0; i < 8; i++) {
        int r = wid * 8 + i;
        int n = rowBase + r;
        uint4 frag = make_uint4(0u, 0u, 0u, 0u);
        if (n < M) {
            int tk = (lane < Tt) ? tok[n * Tt + lane] : 0;
            float4 s = make_float4(0.f, 0.f, 0.f, 0.f);
#pragma unroll
            for (int j = 0; j < Tt; j++) {
                int tv = __shfl_sync(0xffffffffu, tk, j);
                float4 v = ((const float4*)emb)[(size_t)tv * 32 + lane];
                s.x += v.x; s.y += v.y; s.z += v.z; s.w += v.w;
            }
            const float inv = 1.0f / Tt;
            frag.x = f2tf(fmaxf(s.x * inv, 0.f));
            frag.y = f2tf(fmaxf(s.y * inv, 0.f));
            frag.z = f2tf(fmaxf(s.z * inv, 0.f));
            frag.w = f2tf(fmaxf(s.w * inv, 0.f));
        }
        *(uint4*)(As + r * ASTR + lane * 4) = frag;
    }
    __syncthreads();

    int warpM = wid & 1, warpN = wid >> 1;
    int gid = lane >> 2, tg = lane & 3;
    float acc[2][4][4];
    mma_tile256(As, Ws, acc, warpM, warpN, gid, tg);

#pragma unroll
    for (int mi = 0; mi < 2; mi++) {
#pragma unroll
        for (int rr = 0; rr < 2; rr++) {
            int r = rowBase + warpM * 32 + mi * 16 + gid + rr * 8;
            if (r >= M) continue;
#pragma unroll
            for (int ni = 0; ni < 4; ni++) {
                int c0 = warpN * 32 + ni * 8 + 2 * tg;
                float v0 = fmaxf(acc[mi][ni][rr * 2 + 0] + bias[c0], 0.f);
                float v1 = fmaxf(acc[mi][ni][rr * 2 + 1] + bias[c0 + 1], 0.f);
                *(float2*)(Cout + (size_t)r * Cc + c0) = make_float2(v0, v1);
            }
        }
    }
}

// ---------------- multi-pass GEMM: A loaded once, NP weight passes ----------------
struct MG5 {
    const unsigned* W[5];
    const float* B[5];
    float* C[5];
};
template <int NP>
__global__ void __launch_bounds__(256, 2)
gemm_multi(const float* __restrict__ A, MG5 p, int M) {
    extern __shared__ unsigned smu[];
    unsigned* Ws = smu;
    unsigned* As = smu + 128 * WSTR;
    int t = threadIdx.x;
    int rowBase = blockIdx.x * MROWS;

    load_A256<0>(A, As, t, rowBase, M);

    int lane = t & 31, wid = t >> 5;
    int warpM = wid & 1, warpN = wid >> 1;
    int gid = lane >> 2, tg = lane & 3;

#pragma unroll
    for (int it = 0; it < NP; it++) {
        __syncthreads();
        load_W256(p.W[it], Ws, t);
        __syncthreads();

        float acc[2][4][4];
        mma_tile256(As, Ws, acc, warpM, warpN, gid, tg);

        const float* bias = p.B[it];
        float* Cout = p.C[it];
#pragma unroll
        for (int mi = 0; mi < 2; mi++) {
#pragma unroll
            for (int rr = 0; rr < 2; rr++) {
                int r = rowBase + warpM * 32 + mi * 16 + gid + rr * 8;
                if (r >= M) continue;
#pragma unroll
                for (int ni = 0; ni < 4; ni++) {
                    int c0 = warpN * 32 + ni * 8 + 2 * tg;
                    float v0 = acc[mi][ni][rr * 2 + 0] + bias[c0];
                    float v1 = acc[mi][ni][rr * 2 + 1] + bias[c0 + 1];
                    *(float2*)(Cout + (size_t)r * Cc + c0) = make_float2(v0, v1);
                }
            }
        }
    }
}

// ---------------- online-softmax attention pass (per dst,head) ----------------
__device__ __forceinline__ void attn_pass(
    const float* __restrict__ KR, const float* __restrict__ VR,
    const int* __restrict__ rp, const int* __restrict__ col,
    int dst, int h, const float4* q, float ps, float4* o) {
    int beg = rp[dst], end = rp[dst + 1];
    float m = -INFINITY, S = 0.f;
    float4 a0 = make_float4(0.f, 0.f, 0.f, 0.f), a1 = a0, a2 = a0, a3 = a0;
    for (int j = beg; j < end; j++) {
        int s = col[j];
        const float4* k4 = (const float4*)(KR + (size_t)s * Cc + h * 16);
        float4 ka = k4[0], kb = k4[1], kc = k4[2], kd = k4[3];
        float dot = ka.x * q[0].x + ka.y * q[0].y + ka.z * q[0].z + ka.w * q[0].w
                  + kb.x * q[1].x + kb.y * q[1].y + kb.z * q[1].z + kb.w * q[1].w
                  + kc.x * q[2].x + kc.y * q[2].y + kc.z * q[2].z + kc.w * q[2].w
                  + kd.x * q[3].x + kd.y * q[3].y + kd.z * q[3].z + kd.w * q[3].w;
        float lg = dot * ps;
        float mn = fmaxf(m, lg);
        float scale = __expf(m - mn);
        float w = __expf(lg - mn);
        S = S * scale + w;
        m = mn;
        const float4* v4 = (const float4*)(VR + (size_t)s * Cc + h * 16);
        float4 v0 = v4[0], v1 = v4[1], v2 = v4[2], v3 = v4[3];
        a0.x = a0.x * scale + w * v0.x; a0.y = a0.y * scale + w * v0.y;
        a0.z = a0.z * scale + w * v0.z; a0.w = a0.w * scale + w * v0.w;
        a1.x = a1.x * scale + w * v1.x; a1.y = a1.y * scale + w * v1.y;
        a1.z = a1.z * scale + w * v1.z; a1.w = a1.w * scale + w * v1.w;
        a2.x = a2.x * scale + w * v2.x; a2.y = a2.y * scale + w * v2.y;
        a2.z = a2.z * scale + w * v2.z; a2.w = a2.w * scale + w * v2.w;
        a3.x = a3.x * scale + w * v3.x; a3.y = a3.y * scale + w * v3.y;
        a3.z = a3.z * scale + w * v3.z; a3.w = a3.w * scale + w * v3.w;
    }
    float inv = 1.0f / (S + 1e-16f);
    o[0].x += a0.x * inv; o[0].y += a0.y * inv; o[0].z += a0.z * inv; o[0].w += a0.w * inv;
    o[1].x += a1.x * inv; o[1].y += a1.y * inv; o[1].z += a1.z * inv; o[1].w += a1.w * inv;
    o[2].x += a2.x * inv; o[2].y += a2.y * inv; o[2].z += a2.z * inv; o[2].w += a2.w * inv;
    o[3].x += a3.x * inv; o[3].y += a3.y * inv; o[3].z += a3.z * inv; o[3].w += a3.w * inv;
}

// ---------------- fused attention + output-projection (gelu pre, skip-gate epi) ----------------
template <int TWO>
__global__ void __launch_bounds__(256, 2)
attn_out(const float* __restrict__ Q,
         const float* __restrict__ KRa, const float* __restrict__ VRa,
         const int* __restrict__ rpa, const int* __restrict__ cola,
         const float* __restrict__ prela,
         const float* __restrict__ KRb, const float* __restrict__ VRb,
         const int* __restrict__ rpb, const int* __restrict__ colb,
         const float* __restrict__ prelb,
         const unsigned* __restrict__ Wt, const float* __restrict__ bias,
         const float* __restrict__ skipP, const float* __restrict__ Xold,
         float* __restrict__ Out, int Ndst) {
    extern __shared__ unsigned smu[];
    unsigned* Ws = smu;
    unsigned* As = smu + 128 * WSTR;
    int t = threadIdx.x;
    int rowBase = blockIdx.x * MROWS;

    load_W256(Wt, Ws, t);   // overlaps with gathers

    float psa = __ldg(&prela[0 /*dummy*/]) * 0.f;  // avoid unused warnings pattern
    (void)psa;

#pragma unroll
    for (int uu = 0; uu < 2; uu++) {
        int u = t + uu * 256;            // 0..511
        int dstL = u >> 3, h = u & 7;
        int dst = rowBase + dstL;
        float4 o[4] = {make_float4(0.f, 0.f, 0.f, 0.f), make_float4(0.f, 0.f, 0.f, 0.f),
                       make_float4(0.f, 0.f, 0.f, 0.f), make_float4(0.f, 0.f, 0.f, 0.f)};
        if (dst < Ndst) {
            const float4* q4 = (const float4*)(Q + (size_t)dst * Cc + h * 16);
            float4 q[4] = {q4[0], q4[1], q4[2], q4[3]};
            attn_pass(KRa, VRa, rpa, cola, dst, h, q, __ldg(&prela[h]) * 0.25f, o);
            if (TWO) attn_pass(KRb, VRb, rpb, colb, dst, h, q, __ldg(&prelb[h]) * 0.25f, o);
        }
        unsigned* dstp = As + dstL * ASTR + h * 16;
#pragma unroll
        for (int i = 0; i < 4; i++) {
            uint4 frag;
            frag.x = f2tf(gelu_tanh(o[i].x));
            frag.y = f2tf(gelu_tanh(o[i].y));
            frag.z = f2tf(gelu_tanh(o[i].z));
            frag.w = f2tf(gelu_tanh(o[i].w));
            *(uint4*)(dstp + i * 4) = frag;
        }
    }
    __syncthreads();

    int lane = t & 31, wid = t >> 5;
    int warpM = wid & 1, warpN = wid >> 1;
    int gid = lane >> 2, tg = lane & 3;
    float acc[2][4][4];
    mma_tile256(As, Ws, acc, warpM, warpN, gid, tg);

    float g = 1.0f / (1.0f + expf(-__ldg(skipP)));
#pragma unroll
    for (int mi = 0; mi < 2; mi++) {
#pragma unroll
        for (int rr = 0; rr < 2; rr++) {
            int r = rowBase + warpM * 32 + mi * 16 + gid + rr * 8;
            if (r >= Ndst) continue;
#pragma unroll
            for (int ni = 0; ni < 4; ni++) {
                int c0 = warpN * 32 + ni * 8 + 2 * tg;
                float v0 = acc[mi][ni][rr * 2 + 0] + bias[c0];
                float v1 = acc[mi][ni][rr * 2 + 1] + bias[c0 + 1];
                float2 xo = *(const float2*)(Xold + (size_t)r * Cc + c0);
                v0 = g * v0 + (1.0f - g) * xo.x;
                v1 = g * v1 + (1.0f - g) * xo.y;
                *(float2*)(Out + (size_t)r * Cc + c0) = make_float2(v0, v1);
            }
        }
    }
}

// ---------------- host orchestration ----------------
static inline int cdiv(int a, int b) { return (a + b - 1) / b; }

extern "C" void kernel_launch(void* const* d_in, const int* in_sizes, int n_in,
                              void* d_out, int out_size) {
    const int* tok_s = (const int*)d_in[0];
    const int* tok_f = (const int*)d_in[1];
    const int* esrc[3] = {(const int*)d_in[2], (const int*)d_in[4], (const int*)d_in[6]};
    const int* edst[3] = {(const int*)d_in[3], (const int*)d_in[5], (const int*)d_in[7]};
    const float* emb   = (const float*)d_in[8];
    const float* lin_w = (const float*)d_in[9];
    const float* lin_b = (const float*)d_in[10];
    const float* kw = (const float*)d_in[11];
    const float* kb = (const float*)d_in[12];
    const float* qw = (const float*)d_in[13];
    const float* qb = (const float*)d_in[14];
    const float* vw = (const float*)d_in[15];
    const float* vb = (const float*)d_in[16];
    const float* aw = (const float*)d_in[17];
    const float* ab = (const float*)d_in[18];
    const float* skip  = (const float*)d_in[19];
    const float* a_rel = (const float*)d_in[20];
    const float* m_rel = (const float*)d_in[21];
    const float* p_rel = (const float*)d_in[22];
    const int E = in_sizes[2];

    float *gx, *gq, *gkr0, *gvr0, *gkr1, *gvr1, *gkr2, *gvr2, *gbc;
    unsigned* gwtf;
    int *growptr, *gcursor, *gcol, *gbsum;
    cudaGetSymbolAddress((void**)&gx,   g_x);
    cudaGetSymbolAddress((void**)&gq,   g_q);
    cudaGetSymbolAddress((void**)&gkr0, g_kr0);
    cudaGetSymbolAddress((void**)&gvr0, g_vr0);
    cudaGetSymbolAddress((void**)&gkr1, g_kr1);
    cudaGetSymbolAddress((void**)&gvr1, g_vr1);
    cudaGetSymbolAddress((void**)&gkr2, g_kr2);
    cudaGetSymbolAddress((void**)&gvr2, g_vr2);
    cudaGetSymbolAddress((void**)&gwtf, g_wtf);
    cudaGetSymbolAddress((void**)&gbc,  g_bc);
    cudaGetSymbolAddress((void**)&growptr, g_rowptr);
    cudaGetSymbolAddress((void**)&gcursor, g_cursor);
    cudaGetSymbolAddress((void**)&gcol, g_col);
    cudaGetSymbolAddress((void**)&gbsum, g_bsum);

    const size_t smem1 = (size_t)(128 * WSTR + MROWS * ASTR) * sizeof(float);   // 103424
    cudaFuncSetAttribute(enc_gemm, cudaFuncAttributeMaxDynamicSharedMemorySize, (int)smem1);
    cudaFuncSetAttribute(gemm_multi<5>, cudaFuncAttributeMaxDynamicSharedMemorySize, (int)smem1);
    cudaFuncSetAttribute(gemm_multi<3>, cudaFuncAttributeMaxDynamicSharedMemorySize, (int)smem1);
    cudaFuncSetAttribute(attn_out<1>, cudaFuncAttributeMaxDynamicSharedMemorySize, (int)smem1);
    cudaFuncSetAttribute(attn_out<0>, cudaFuncAttributeMaxDynamicSharedMemorySize, (int)smem1);

    const int NNODES[2] = {NS, NF};
    const size_t OFF[2] = {0, (size_t)NS * Cc};
    #define T_LIN(t)  ((size_t)(t) * WTILE)
    #define T_Q(wi)   ((size_t)(2 + (wi)) * WTILE)
    #define T_A(wi)   ((size_t)(6 + (wi)) * WTILE)
    #define T_C(c)    ((size_t)(10 + (c)) * WTILE)

    // launch order: ncu profiles launch idx 3 -> gemm_multi<5> stmt l0 there
    {
        dim3 grid(128, 22);
        prep_compose<<<grid, 128>>>(lin_w, qw, aw, kw, vw, kb, vb, a_rel, m_rel,
                                    gwtf, gbc);                                        // 0
    }
    enc_gemm<<<cdiv(NS, MROWS), 256, smem1>>>(
        tok_s, emb, gwtf + T_LIN(0), lin_b, gx, NS);                                   // 1
    enc_gemm<<<cdiv(NF, MROWS), 256, smem1>>>(
        tok_f, emb, gwtf + T_LIN(1), lin_b + Cc, gx + OFF[1], NF);                     // 2
    {
        MG5 p;
        p.W[0] = gwtf + T_Q(0);  p.B[0] = qb;            p.C[0] = gq;
        p.W[1] = gwtf + T_C(0);  p.B[1] = gbc + 0 * Cc;  p.C[1] = gkr0;
        p.W[2] = gwtf + T_C(1);  p.B[2] = gbc + 1 * Cc;  p.C[2] = gvr0;
        p.W[3] = gwtf + T_C(2);  p.B[3] = gbc + 2 * Cc;  p.C[3] = gkr1;
        p.W[4] = gwtf + T_C(3);  p.B[4] = gbc + 3 * Cc;  p.C[4] = gvr1;
        gemm_multi<5><<<cdiv(NS, MROWS), 256, smem1>>>(gx, p, NS);                     // 3 (profiled)
    }

    // CSR build (edges fixed; rebuilt deterministically each call)
    const int EDT[3] = {0, 1, 0};
    for (int r = 0; r < 3; r++) {
        int Ndst = NNODES[EDT[r]];
        int n = Ndst + 1;
        int* rp = growptr + r * (NS + 1);
        zero_i<<<cdiv(n, 256), 256>>>(rp, n);
        hist_kernel<<<cdiv(E, 256), 256>>>(edst[r], rp, E);
        int nb = cdiv(n, 1024);
        scan_blk<<<nb, 1024>>>(rp, gbsum, n);
        scan_top<<<1, 32>>>(gbsum, nb);
        scan_add<<<nb, 1024>>>(rp, gbsum, n);
        copy_i<<<cdiv(n, 256), 256>>>(rp, gcursor, n);
        scatter_kernel<<<cdiv(E, 256), 256>>>(esrc[r], edst[r], gcursor, gcol + r * EMAX, E);
    }

    for (int l = 0; l < 2; l++) {
        if (l == 1) {
            MG5 p;
            p.W[0] = gwtf + T_Q(2);  p.B[0] = qb + 2 * Cc;  p.C[0] = gq;
            p.W[1] = gwtf + T_C(6);  p.B[1] = gbc + 6 * Cc; p.C[1] = gkr0;
            p.W[2] = gwtf + T_C(7);  p.B[2] = gbc + 7 * Cc; p.C[2] = gvr0;
            p.W[3] = gwtf + T_C(8);  p.B[3] = gbc + 8 * Cc; p.C[3] = gkr1;
            p.W[4] = gwtf + T_C(9);  p.B[4] = gbc + 9 * Cc; p.C[4] = gvr1;
            gemm_multi<5><<<cdiv(NS, MROWS), 256, smem1>>>(gx, p, NS);
        }
        {
            MG5 p;
            p.W[0] = gwtf + T_Q(l * 2 + 1);   p.B[0] = qb + (l * 2 + 1) * Cc;   p.C[0] = gq + OFF[1];
            p.W[1] = gwtf + T_C(l * 6 + 4);   p.B[1] = gbc + (l * 6 + 4) * Cc;  p.C[1] = gkr2;
            p.W[2] = gwtf + T_C(l * 6 + 5);   p.B[2] = gbc + (l * 6 + 5) * Cc;  p.C[2] = gvr2;
            gemm_multi<3><<<cdiv(NF, MROWS), 256, smem1>>>(gx + OFF[1], p, NF);
        }

        float* out_s = (l == 1) ? ((float*)d_out) : gx;
        float* out_f = (l == 1) ? ((float*)d_out + OFF[1]) : (gx + OFF[1]);

        attn_out<1><<<cdiv(NS, MROWS), 256, smem1>>>(
            gq,
            gkr0, gvr0, growptr + 0 * (NS + 1), gcol + 0 * EMAX, p_rel + (size_t)(l * 3 + 0) * Hh,
            gkr2, gvr2, growptr + 2 * (NS + 1), gcol + 2 * EMAX, p_rel + (size_t)(l * 3 + 2) * Hh,
            gwtf + T_A(l * 2 + 0), ab + (size_t)(l * 2 + 0) * Cc,
            skip + (l * 2 + 0), gx, out_s, NS);
        attn_out<0><<<cdiv(NF, MROWS), 256, smem1>>>(
            gq + OFF[1],
            gkr1, gvr1, growptr + 1 * (NS + 1), gcol + 1 * EMAX, p_rel + (size_t)(l * 3 + 1) * Hh,
            nullptr, nullptr, nullptr, nullptr, nullptr,
            gwtf + T_A(l * 2 + 1), ab + (size_t)(l * 2 + 1) * Cc,
            skip + (l * 2 + 1), gx + OFF[1], out_f, NF);
    }
}

// round 11
// speedup vs baseline: 1.0522x; 1.0522x over previous
#include <cuda_runtime.h>
#include <math.h>

#define Cc 128
#define Hh 8
#define Dd 16
#define Tt 16
#define NS 100000
#define NF 50000
#define NT 150000
#define EMAX 200000
#define CCx (Cc * Cc)

#define ASTR 136             // A smem stride (mod 32 == 8: conflict-free LDS.64)
#define WSTR 136             // W smem stride ([n][k_perm] layout)
#define WTILE (128 * WSTR)   // u32 per pre-swizzled weight tile

// ---------------- scratch (device globals; no allocation) ----------------
__device__ float g_e  [(size_t)NT * Cc];
__device__ float g_x  [(size_t)NT * Cc];
__device__ float g_q  [(size_t)NT * Cc];
__device__ float g_kr0[(size_t)NS * Cc];
__device__ float g_vr0[(size_t)NS * Cc];
__device__ float g_kr1[(size_t)NS * Cc];
__device__ float g_vr1[(size_t)NS * Cc];
__device__ float g_kr2[(size_t)NF * Cc];
__device__ float g_vr2[(size_t)NF * Cc];
__device__ float g_agg[(size_t)NT * Cc];
__device__ unsigned g_wtf[(size_t)22 * WTILE];
__device__ float g_bc [12 * Cc];
__device__ int g_rowptr[3 * (NS + 1)];
__device__ int g_cursor[NS + 1];
__device__ int g_col[3 * EMAX];
__device__ int g_bsum[256];

// ---------------- helpers ----------------
__device__ __forceinline__ float gelu_tanh(float x) {
    float x3 = x * x * x;
    return 0.5f * x * (1.0f + tanhf(0.7978845608028654f * (x + 0.044715f * x3)));
}
__device__ __forceinline__ unsigned f2tf(float f) {
    unsigned r; asm("cvt.rna.tf32.f32 %0, %1;" : "=r"(r) : "f"(f)); return r;
}
// k-pair permutation: (k=tg, k=tg+4) become adjacent words
__device__ __host__ __forceinline__ int kperm(int k) {
    return (k & ~7) | (2 * (k & 3)) | ((k >> 2) & 1);
}

// ---------------- small utility kernels ----------------
__global__ void zero_i(int* p, int n) {
    int i = blockIdx.x * blockDim.x + threadIdx.x;
    if (i < n) p[i] = 0;
}
__global__ void copy_i(const int* a, int* b, int n) {
    int i = blockIdx.x * blockDim.x + threadIdx.x;
    if (i < n) b[i] = a[i];
}

// ---------------- CSR build ----------------
__global__ void hist_kernel(const int* __restrict__ dst, int* __restrict__ rowptr, int E) {
    int e = blockIdx.x * blockDim.x + threadIdx.x;
    if (e < E) atomicAdd(&rowptr[dst[e] + 1], 1);
}
__global__ void scan_blk(int* data, int* bsum, int n) {
    __shared__ int sm[1024];
    int i = blockIdx.x * 1024 + threadIdx.x;
    int v = (i < n) ? data[i] : 0;
    sm[threadIdx.x] = v;
    __syncthreads();
    for (int ofs = 1; ofs < 1024; ofs <<= 1) {
        int t = (threadIdx.x >= ofs) ? sm[threadIdx.x - ofs] : 0;
        __syncthreads();
        sm[threadIdx.x] += t;
        __syncthreads();
    }
    if (i < n) data[i] = sm[threadIdx.x];
    if (threadIdx.x == 1023) bsum[blockIdx.x] = sm[1023];
}
__global__ void scan_top(int* bsum, int nb) {
    if (threadIdx.x == 0) {
        int acc = 0;
        for (int i = 0; i < nb; i++) { int t = bsum[i]; bsum[i] = acc; acc += t; }
    }
}
__global__ void scan_add(int* data, const int* bsum, int n) {
    int i = blockIdx.x * 1024 + threadIdx.x;
    if (i < n) data[i] += bsum[blockIdx.x];
}
__global__ void scatter_kernel(const int* __restrict__ src, const int* __restrict__ dst,
                               int* __restrict__ cursor, int* __restrict__ col, int E) {
    int e = blockIdx.x * blockDim.x + threadIdx.x;
    if (e < E) {
        int pos = atomicAdd(&cursor[dst[e]], 1);
        col[pos] = src[e];
    }
}

// ---------------- encoder: relu(mean(emb[tok])), warp per node ----------------
__global__ void enc_kernel(const int* __restrict__ tok, const float* __restrict__ emb,
                           float* __restrict__ out, int N) {
    int warp = (blockIdx.x * blockDim.x + threadIdx.x) >> 5;
    int lane = threadIdx.x & 31;
    if (warp >= N) return;
    int tk = (lane < Tt) ? tok[warp * Tt + lane] : 0;
    float4 s = make_float4(0.f, 0.f, 0.f, 0.f);
#pragma unroll
    for (int i = 0; i < Tt; i++) {
        int t = __shfl_sync(0xffffffffu, tk, i);
        float4 v = ((const float4*)emb)[(size_t)t * 32 + lane];
        s.x += v.x; s.y += v.y; s.z += v.z; s.w += v.w;
    }
    const float inv = 1.0f / Tt;
    float4 o = make_float4(fmaxf(s.x * inv, 0.f), fmaxf(s.y * inv, 0.f),
                           fmaxf(s.z * inv, 0.f), fmaxf(s.w * inv, 0.f));
    ((float4*)out)[(size_t)warp * 32 + lane] = o;
}

// ---------------- prep + compose: 22 tiles, layout [n][kperm] tf32 ----------------
// tiles: 0-1 lin, 2-5 qw, 6-9 aw, 10-21 composed (comp = l*6 + r*2 + isV)
__global__ void prep_compose(const float* __restrict__ lin_w, const float* __restrict__ qw,
                             const float* __restrict__ aw,
                             const float* __restrict__ kw, const float* __restrict__ vw,
                             const float* __restrict__ kb, const float* __restrict__ vb,
                             const float* __restrict__ a_rel, const float* __restrict__ m_rel,
                             unsigned* __restrict__ wtf, float* __restrict__ bc) {
    int m = blockIdx.y;
    int k = blockIdx.x;      // input-dim index (0..127)
    int t = threadIdx.x;     // output col n (0..127)
    int qk = kperm(k);
    if (m < 10) {
        const float* src = (m < 2) ? lin_w + (size_t)m * CCx
                         : (m < 6) ? qw + (size_t)(m - 2) * CCx
                                   : aw + (size_t)(m - 6) * CCx;
        wtf[(size_t)m * WTILE + t * WSTR + qk] = f2tf(src[k * 128 + t]);
        return;
    }
    int comp = m - 10;
    int l = comp / 6, c6 = comp % 6, r = c6 >> 1, isV = c6 & 1;
    int st = (r == 2) ? 1 : 0;
    const float* W = (isV ? vw : kw) + (size_t)(l * 2 + st) * CCx;
    const float* B = (isV ? vb : kb) + (size_t)(l * 2 + st) * Cc;
    const float* A = (isV ? m_rel : a_rel) + (size_t)(l * 3 + r) * Hh * Dd * Dd;
    __shared__ float sw[128];
    __shared__ float sa[2048];
    sw[t] = W[k * 128 + t];
#pragma unroll
    for (int u = 0; u < 16; u++) sa[t + 128 * u] = A[t + 128 * u];
    __syncthreads();
    int h = t >> 4, e = t & 15;
    float s = 0.f;
#pragma unroll
    for (int d = 0; d < 16; d++) s = fmaf(sw[h * 16 + d], sa[h * 256 + d * 16 + e], s);
    wtf[(size_t)m * WTILE + t * WSTR + qk] = f2tf(s);
    if (k == 0) {
        float sb = 0.f;
#pragma unroll
        for (int d = 0; d < 16; d++) sb = fmaf(B[h * 16 + d], sa[h * 256 + d * 16 + e], sb);
        bc[comp * Cc + t] = sb;
    }
}

// ---------------- GEMM blocks: 128x128 tile, 512 threads, warp grid 4x4 ----------------
__device__ __forceinline__ void load_W512(const unsigned* __restrict__ Wt, unsigned* Ws, int t) {
    const float4* src = (const float4*)Wt;
    float4* dst = (float4*)Ws;
#pragma unroll
    for (int u = 0; u < 9; u++) {
        int f = t + 512 * u;
        if (f < WTILE / 4) dst[f] = src[f];
    }
}

// A tile stored with kperm column permutation (4x STS.32 per float4)
template <int PRE>
__device__ __forceinline__ void load_A512(const float* __restrict__ A, unsigned* As,
                                          int t, int rowBase, int M) {
#pragma unroll
    for (int u = 0; u < 8; u++) {
        int f = t + 512 * u;          // 0..4095
        int r = f >> 5, c4 = f & 31;
        int gr = rowBase + r;
        float4 v = make_float4(0.f, 0.f, 0.f, 0.f);
        if (gr < M) v = ((const float4*)A)[(size_t)gr * 32 + c4];
        if (PRE == 1) {
            v.x = gelu_tanh(v.x); v.y = gelu_tanh(v.y);
            v.z = gelu_tanh(v.z); v.w = gelu_tanh(v.w);
        }
        unsigned* p = As + r * ASTR + ((c4 >> 1) << 3) + (c4 & 1);
        p[0] = f2tf(v.x); p[2] = f2tf(v.y); p[4] = f2tf(v.z); p[6] = f2tf(v.w);
    }
}

__device__ __forceinline__ void mma_tile512(const unsigned* As, const unsigned* Ws,
                                            float acc[2][4][4], int warpM, int warpN,
                                            int gid, int tg) {
#pragma unroll
    for (int mi = 0; mi < 2; mi++)
#pragma unroll
        for (int ni = 0; ni < 4; ni++)
#pragma unroll
            for (int j = 0; j < 4; j++) acc[mi][ni][j] = 0.0f;
#pragma unroll
    for (int kc = 0; kc < 16; kc++) {
        int k0 = kc * 8;
        unsigned a[2][4];
#pragma unroll
        for (int mi = 0; mi < 2; mi++) {
            const unsigned* Ap = As + (warpM * 32 + mi * 16 + gid) * ASTR + k0 + 2 * tg;
            uint2 lo = *(const uint2*)Ap;              // (row gid,   k=tg | k=tg+4)
            uint2 hi = *(const uint2*)(Ap + 8 * ASTR); // (row gid+8, k=tg | k=tg+4)
            a[mi][0] = lo.x; a[mi][1] = hi.x; a[mi][2] = lo.y; a[mi][3] = hi.y;
        }
        unsigned b[4][2];
#pragma unroll
        for (int ni = 0; ni < 4; ni++) {
            int n = warpN * 32 + ni * 8 + gid;
            uint2 bb = *(const uint2*)(Ws + n * WSTR + k0 + 2 * tg);  // (k=tg, k=tg+4)
            b[ni][0] = bb.x; b[ni][1] = bb.y;
        }
#pragma unroll
        for (int mi = 0; mi < 2; mi++)
#pragma unroll
            for (int ni = 0; ni < 4; ni++)
                asm volatile(
                    "mma.sync.aligned.m16n8k8.row.col.f32.tf32.tf32.f32 "
                    "{%0,%1,%2,%3},{%4,%5,%6,%7},{%8,%9},{%0,%1,%2,%3};"
                    : "+f"(acc[mi][ni][0]), "+f"(acc[mi][ni][1]),
                      "+f"(acc[mi][ni][2]), "+f"(acc[mi][ni][3])
                    : "r"(a[mi][0]), "r"(a[mi][1]), "r"(a[mi][2]), "r"(a[mi][3]),
                      "r"(b[ni][0]), "r"(b[ni][1]));
    }
}

// single GEMM on pre-swizzled W.  EPI: 1 relu, 2 skip-gate.
template <int PRE, int EPI>
__global__ void __launch_bounds__(512, 1)
gemm_tf32(const float* __restrict__ A, const unsigned* __restrict__ Wt,
          const float* __restrict__ bias, float* __restrict__ Cout,
          const float* __restrict__ Xold, const float* __restrict__ skipP, int M) {
    extern __shared__ unsigned smu[];
    unsigned* Ws = smu;
    unsigned* As = smu + 128 * WSTR;
    int t = threadIdx.x;
    int rowBase = blockIdx.x * 128;

    load_W512(Wt, Ws, t);
    load_A512<PRE>(A, As, t, rowBase, M);
    __syncthreads();

    int lane = t & 31, wid = t >> 5;
    int warpM = wid & 3, warpN = wid >> 2;
    int gid = lane >> 2, tg = lane & 3;

    float acc[2][4][4];
    mma_tile512(As, Ws, acc, warpM, warpN, gid, tg);

    float g = 1.0f;
    if (EPI == 2) g = 1.0f / (1.0f + expf(-__ldg(skipP)));
#pragma unroll
    for (int mi = 0; mi < 2; mi++) {
#pragma unroll
        for (int rr = 0; rr < 2; rr++) {
            int r = rowBase + warpM * 32 + mi * 16 + gid + rr * 8;
            if (r >= M) continue;
#pragma unroll
            for (int ni = 0; ni < 4; ni++) {
                int c0 = warpN * 32 + ni * 8 + 2 * tg;
                float v0 = acc[mi][ni][rr * 2 + 0] + bias[c0];
                float v1 = acc[mi][ni][rr * 2 + 1] + bias[c0 + 1];
                if (EPI == 1) { v0 = fmaxf(v0, 0.f); v1 = fmaxf(v1, 0.f); }
                if (EPI == 2) {
                    float2 xo = *(const float2*)(Xold + (size_t)r * Cc + c0);
                    v0 = g * v0 + (1.0f - g) * xo.x;
                    v1 = g * v1 + (1.0f - g) * xo.y;
                }
                *(float2*)(Cout + (size_t)r * Cc + c0) = make_float2(v0, v1);
            }
        }
    }
}

// multi-pass GEMM: A loaded once, NP weight passes.
struct MG5 {
    const unsigned* W[5];
    const float* B[5];
    float* C[5];
};
template <int NP>
__global__ void __launch_bounds__(512, 1)
gemm_multi(const float* __restrict__ A, MG5 p, int M) {
    extern __shared__ unsigned smu[];
    unsigned* Ws = smu;
    unsigned* As = smu + 128 * WSTR;
    int t = threadIdx.x;
    int rowBase = blockIdx.x * 128;

    load_A512<0>(A, As, t, rowBase, M);

    int lane = t & 31, wid = t >> 5;
    int warpM = wid & 3, warpN = wid >> 2;
    int gid = lane >> 2, tg = lane & 3;

#pragma unroll
    for (int it = 0; it < NP; it++) {
        __syncthreads();                 // Ws free (and A visible on it=0)
        load_W512(p.W[it], Ws, t);
        __syncthreads();

        float acc[2][4][4];
        mma_tile512(As, Ws, acc, warpM, warpN, gid, tg);

        const float* bias = p.B[it];
        float* Cout = p.C[it];
#pragma unroll
        for (int mi = 0; mi < 2; mi++) {
#pragma unroll
            for (int rr = 0; rr < 2; rr++) {
                int r = rowBase + warpM * 32 + mi * 16 + gid + rr * 8;
                if (r >= M) continue;
#pragma unroll
                for (int ni = 0; ni < 4; ni++) {
                    int c0 = warpN * 32 + ni * 8 + 2 * tg;
                    float v0 = acc[mi][ni][rr * 2 + 0] + bias[c0];
                    float v1 = acc[mi][ni][rr * 2 + 1] + bias[c0 + 1];
                    *(float2*)(Cout + (size_t)r * Cc + c0) = make_float2(v0, v1);
                }
            }
        }
    }
}

// ---------------- single-pass online-softmax CSR attention (1 thread per dst,head) ----------------
__device__ __forceinline__ void attn_pass(
    const float* __restrict__ KR, const float* __restrict__ VR,
    const int* __restrict__ rp, const int* __restrict__ col,
    int dst, int h, const float4* q, float ps, float4* o) {
    int beg = rp[dst], end = rp[dst + 1];
    float m = -INFINITY, S = 0.f;
    float4 a0 = make_float4(0.f, 0.f, 0.f, 0.f), a1 = a0, a2 = a0, a3 = a0;
    for (int j = beg; j < end; j++) {
        int s = col[j];
        const float4* k4 = (const float4*)(KR + (size_t)s * Cc + h * 16);
        float4 ka = k4[0], kb = k4[1], kc = k4[2], kd = k4[3];
        float dot = ka.x * q[0].x + ka.y * q[0].y + ka.z * q[0].z + ka.w * q[0].w
                  + kb.x * q[1].x + kb.y * q[1].y + kb.z * q[1].z + kb.w * q[1].w
                  + kc.x * q[2].x + kc.y * q[2].y + kc.z * q[2].z + kc.w * q[2].w
                  + kd.x * q[3].x + kd.y * q[3].y + kd.z * q[3].z + kd.w * q[3].w;
        float lg = dot * ps;
        float mn = fmaxf(m, lg);
        float scale = __expf(m - mn);
        float w = __expf(lg - mn);
        S = S * scale + w;
        m = mn;
        const float4* v4 = (const float4*)(VR + (size_t)s * Cc + h * 16);
        float4 v0 = v4[0], v1 = v4[1], v2 = v4[2], v3 = v4[3];
        a0.x = a0.x * scale + w * v0.x; a0.y = a0.y * scale + w * v0.y;
        a0.z = a0.z * scale + w * v0.z; a0.w = a0.w * scale + w * v0.w;
        a1.x = a1.x * scale + w * v1.x; a1.y = a1.y * scale + w * v1.y;
        a1.z = a1.z * scale + w * v1.z; a1.w = a1.w * scale + w * v1.w;
        a2.x = a2.x * scale + w * v2.x; a2.y = a2.y * scale + w * v2.y;
        a2.z = a2.z * scale + w * v2.z; a2.w = a2.w * scale + w * v2.w;
        a3.x = a3.x * scale + w * v3.x; a3.y = a3.y * scale + w * v3.y;
        a3.z = a3.z * scale + w * v3.z; a3.w = a3.w * scale + w * v3.w;
    }
    float inv = 1.0f / (S + 1e-16f);
    o[0].x += a0.x * inv; o[0].y += a0.y * inv; o[0].z += a0.z * inv; o[0].w += a0.w * inv;
    o[1].x += a1.x * inv; o[1].y += a1.y * inv; o[1].z += a1.z * inv; o[1].w += a1.w * inv;
    o[2].x += a2.x * inv; o[2].y += a2.y * inv; o[2].z += a2.z * inv; o[2].w += a2.w * inv;
    o[3].x += a3.x * inv; o[3].y += a3.y * inv; o[3].z += a3.z * inv; o[3].w += a3.w * inv;
}

template <int TWO>
__global__ void attn_csr(const float* __restrict__ Q,
                         const float* __restrict__ KRa, const float* __restrict__ VRa,
                         const int* __restrict__ rpa, const int* __restrict__ cola,
                         const float* __restrict__ prela,
                         const float* __restrict__ KRb, const float* __restrict__ VRb,
                         const int* __restrict__ rpb, const int* __restrict__ colb,
                         const float* __restrict__ prelb,
                         float* __restrict__ agg, int Ndst) {
    int idx = blockIdx.x * blockDim.x + threadIdx.x;
    if (idx >= Ndst * Hh) return;
    int dst = idx >> 3, h = idx & 7;

    const float4* q4 = (const float4*)(Q + (size_t)dst * Cc + h * 16);
    float4 q[4] = {q4[0], q4[1], q4[2], q4[3]};
    float4 o[4] = {make_float4(0.f, 0.f, 0.f, 0.f), make_float4(0.f, 0.f, 0.f, 0.f),
                   make_float4(0.f, 0.f, 0.f, 0.f), make_float4(0.f, 0.f, 0.f, 0.f)};

    attn_pass(KRa, VRa, rpa, cola, dst, h, q, __ldg(&prela[h]) * 0.25f, o);
    if (TWO) attn_pass(KRb, VRb, rpb, colb, dst, h, q, __ldg(&prelb[h]) * 0.25f, o);

    float4* out4 = (float4*)(agg + (size_t)dst * Cc + h * 16);
    out4[0] = o[0]; out4[1] = o[1]; out4[2] = o[2]; out4[3] = o[3];
}

// ---------------- host orchestration ----------------
static inline int cdiv(int a, int b) { return (a + b - 1) / b; }

extern "C" void kernel_launch(void* const* d_in, const int* in_sizes, int n_in,
                              void* d_out, int out_size) {
    const int* tok_s = (const int*)d_in[0];
    const int* tok_f = (const int*)d_in[1];
    const int* esrc[3] = {(const int*)d_in[2], (const int*)d_in[4], (const int*)d_in[6]};
    const int* edst[3] = {(const int*)d_in[3], (const int*)d_in[5], (const int*)d_in[7]};
    const float* emb   = (const float*)d_in[8];
    const float* lin_w = (const float*)d_in[9];
    const float* lin_b = (const float*)d_in[10];
    const float* kw = (const float*)d_in[11];
    const float* kb = (const float*)d_in[12];
    const float* qw = (const float*)d_in[13];
    const float* qb = (const float*)d_in[14];
    const float* vw = (const float*)d_in[15];
    const float* vb = (const float*)d_in[16];
    const float* aw = (const float*)d_in[17];
    const float* ab = (const float*)d_in[18];
    const float* skip  = (const float*)d_in[19];
    const float* a_rel = (const float*)d_in[20];
    const float* m_rel = (const float*)d_in[21];
    const float* p_rel = (const float*)d_in[22];
    const int E = in_sizes[2];

    float *ge, *gx, *gq, *gkr0, *gvr0, *gkr1, *gvr1, *gkr2, *gvr2, *gagg, *gbc;
    unsigned* gwtf;
    int *growptr, *gcursor, *gcol, *gbsum;
    cudaGetSymbolAddress((void**)&ge,   g_e);
    cudaGetSymbolAddress((void**)&gx,   g_x);
    cudaGetSymbolAddress((void**)&gq,   g_q);
    cudaGetSymbolAddress((void**)&gkr0, g_kr0);
    cudaGetSymbolAddress((void**)&gvr0, g_vr0);
    cudaGetSymbolAddress((void**)&gkr1, g_kr1);
    cudaGetSymbolAddress((void**)&gvr1, g_vr1);
    cudaGetSymbolAddress((void**)&gkr2, g_kr2);
    cudaGetSymbolAddress((void**)&gvr2, g_vr2);
    cudaGetSymbolAddress((void**)&gagg, g_agg);
    cudaGetSymbolAddress((void**)&gwtf, g_wtf);
    cudaGetSymbolAddress((void**)&gbc,  g_bc);
    cudaGetSymbolAddress((void**)&growptr, g_rowptr);
    cudaGetSymbolAddress((void**)&gcursor, g_cursor);
    cudaGetSymbolAddress((void**)&gcol, g_col);
    cudaGetSymbolAddress((void**)&gbsum, g_bsum);

    const size_t smem1 = (size_t)(128 * WSTR + 128 * ASTR) * sizeof(float);   // 139264
    cudaFuncSetAttribute(gemm_tf32<0, 1>, cudaFuncAttributeMaxDynamicSharedMemorySize, (int)smem1);
    cudaFuncSetAttribute(gemm_tf32<1, 2>, cudaFuncAttributeMaxDynamicSharedMemorySize, (int)smem1);
    cudaFuncSetAttribute(gemm_multi<5>, cudaFuncAttributeMaxDynamicSharedMemorySize, (int)smem1);
    cudaFuncSetAttribute(gemm_multi<3>, cudaFuncAttributeMaxDynamicSharedMemorySize, (int)smem1);

    const int NNODES[2] = {NS, NF};
    const size_t OFF[2] = {0, (size_t)NS * Cc};
    #define T_LIN(t)  ((size_t)(t) * WTILE)
    #define T_Q(wi)   ((size_t)(2 + (wi)) * WTILE)
    #define T_A(wi)   ((size_t)(6 + (wi)) * WTILE)
    #define T_C(c)    ((size_t)(10 + (c)) * WTILE)

    // launch order: ncu profiles launch idx 3 -> gemm_multi<5> stmt l0 there
    enc_kernel<<<cdiv(NS * 32, 256), 256>>>(tok_s, emb, ge, NS);                      // 0
    {
        dim3 grid(128, 22);
        prep_compose<<<grid, 128>>>(lin_w, qw, aw, kw, vw, kb, vb, a_rel, m_rel,
                                    gwtf, gbc);                                        // 1
    }
    gemm_tf32<0, 1><<<cdiv(NS, 128), 512, smem1>>>(
        ge, gwtf + T_LIN(0), lin_b, gx, nullptr, nullptr, NS);                         // 2
    {
        MG5 p;
        p.W[0] = gwtf + T_Q(0);  p.B[0] = qb;            p.C[0] = gq;
        p.W[1] = gwtf + T_C(0);  p.B[1] = gbc + 0 * Cc;  p.C[1] = gkr0;
        p.W[2] = gwtf + T_C(1);  p.B[2] = gbc + 1 * Cc;  p.C[2] = gvr0;
        p.W[3] = gwtf + T_C(2);  p.B[3] = gbc + 2 * Cc;  p.C[3] = gkr1;
        p.W[4] = gwtf + T_C(3);  p.B[4] = gbc + 3 * Cc;  p.C[4] = gvr1;
        gemm_multi<5><<<cdiv(NS, 128), 512, smem1>>>(gx, p, NS);                       // 3 (profiled)
    }

    enc_kernel<<<cdiv(NF * 32, 256), 256>>>(tok_f, emb, ge + OFF[1], NF);
    gemm_tf32<0, 1><<<cdiv(NF, 128), 512, smem1>>>(
        ge + OFF[1], gwtf + T_LIN(1), lin_b + Cc, gx + OFF[1], nullptr, nullptr, NF);

    // CSR build (once; edges shared across layers)
    const int EDT[3] = {0, 1, 0};
    for (int r = 0; r < 3; r++) {
        int Ndst = NNODES[EDT[r]];
        int n = Ndst + 1;
        int* rp = growptr + r * (NS + 1);
        zero_i<<<cdiv(n, 256), 256>>>(rp, n);
        hist_kernel<<<cdiv(E, 256), 256>>>(edst[r], rp, E);
        int nb = cdiv(n, 1024);
        scan_blk<<<nb, 1024>>>(rp, gbsum, n);
        scan_top<<<1, 32>>>(gbsum, nb);
        scan_add<<<nb, 1024>>>(rp, gbsum, n);
        copy_i<<<cdiv(n, 256), 256>>>(rp, gcursor, n);
        scatter_kernel<<<cdiv(E, 256), 256>>>(esrc[r], edst[r], gcursor, gcol + r * EMAX, E);
    }

    for (int l = 0; l < 2; l++) {
        if (l == 1) {
            MG5 p;
            p.W[0] = gwtf + T_Q(2);  p.B[0] = qb + 2 * Cc;  p.C[0] = gq;
            p.W[1] = gwtf + T_C(6);  p.B[1] = gbc + 6 * Cc; p.C[1] = gkr0;
            p.W[2] = gwtf + T_C(7);  p.B[2] = gbc + 7 * Cc; p.C[2] = gvr0;
            p.W[3] = gwtf + T_C(8);  p.B[3] = gbc + 8 * Cc; p.C[3] = gkr1;
            p.W[4] = gwtf + T_C(9);  p.B[4] = gbc + 9 * Cc; p.C[4] = gvr1;
            gemm_multi<5><<<cdiv(NS, 128), 512, smem1>>>(gx, p, NS);
        }
        {
            MG5 p;
            p.W[0] = gwtf + T_Q(l * 2 + 1);   p.B[0] = qb + (l * 2 + 1) * Cc;   p.C[0] = gq + OFF[1];
            p.W[1] = gwtf + T_C(l * 6 + 4);   p.B[1] = gbc + (l * 6 + 4) * Cc;  p.C[1] = gkr2;
            p.W[2] = gwtf + T_C(l * 6 + 5);   p.B[2] = gbc + (l * 6 + 5) * Cc;  p.C[2] = gvr2;
            gemm_multi<3><<<cdiv(NF, 128), 512, smem1>>>(gx + OFF[1], p, NF);
        }

        attn_csr<1><<<cdiv(NS * Hh, 256), 256>>>(
            gq,
            gkr0, gvr0, growptr + 0 * (NS + 1), gcol + 0 * EMAX, p_rel + (size_t)(l * 3 + 0) * Hh,
            gkr2, gvr2, growptr + 2 * (NS + 1), gcol + 2 * EMAX, p_rel + (size_t)(l * 3 + 2) * Hh,
            gagg, NS);
        attn_csr<0><<<cdiv(NF * Hh, 256), 256>>>(
            gq + OFF[1],
            gkr1, gvr1, growptr + 1 * (NS + 1), gcol + 1 * EMAX, p_rel + (size_t)(l * 3 + 1) * Hh,
            nullptr, nullptr, nullptr, nullptr, nullptr,
            gagg + OFF[1], NF);

        for (int t = 0; t < 2; t++) {
            int wi = (l * 2 + t);
            float* outp = (l == 1) ? ((float*)d_out + OFF[t]) : (gx + OFF[t]);
            gemm_tf32<1, 2><<<cdiv(NNODES[t], 128), 512, smem1>>>(
                gagg + OFF[t], gwtf + T_A(wi), ab + (size_t)wi * Cc,
                outp, gx + OFF[t], skip + wi, NNODES[t]);
        }
    }
}